// round 12
// baseline (speedup 1.0000x reference)
#include <cuda_runtime.h>
#include <math.h>
#include <stdint.h>

#define N_TOK 4096
#define D_DIM 2048
#define N_EXP 8
#define TOPK  2
#define CAP   512
#define PITCH 2052                 // padded W smem row (floats)
#define BLK1  256                  // 8 warps
#define GRID1 128                  // 32 tokens/block, 1 block/SM, single wave
#define STAGE_BYTES 16384          // 2 tokens * 8KB
#define NSLOT 8
#define SMEM_XS_OFF 1024
#define SMEM_WT_OFF (SMEM_XS_OFF + NSLOT * STAGE_BYTES)          // 132096
#define DYN_SMEM (SMEM_WT_OFF + N_EXP * PITCH * 4)               // 197760

// Scratch (static device globals — no allocation)
__device__ int g_choice[N_TOK * TOPK];
__device__ int g_slot[N_TOK * TOPK];

__device__ __forceinline__ unsigned long long fma2(
        unsigned long long a, unsigned long long b, unsigned long long c) {
    unsigned long long d;
    asm("fma.rn.f32x2 %0, %1, %2, %3;" : "=l"(d) : "l"(a), "l"(b), "l"(c));
    return d;
}

__device__ __forceinline__ uint32_t smem_u32(const void* p) {
    return (uint32_t)__cvta_generic_to_shared(p);
}
__device__ __forceinline__ void mbar_init(uint32_t a, uint32_t cnt) {
    asm volatile("mbarrier.init.shared.b64 [%0], %1;" :: "r"(a), "r"(cnt) : "memory");
}
__device__ __forceinline__ void mbar_expect_tx(uint32_t a, uint32_t bytes) {
    asm volatile("mbarrier.arrive.expect_tx.shared.b64 _, [%0], %1;"
                 :: "r"(a), "r"(bytes) : "memory");
}
__device__ __forceinline__ void bulk_g2s(uint32_t dst, const void* src,
                                         uint32_t bytes, uint32_t mbar) {
    asm volatile("cp.async.bulk.shared::cluster.global.mbarrier::complete_tx::bytes "
                 "[%0], [%1], %2, [%3];"
                 :: "r"(dst), "l"(src), "r"(bytes), "r"(mbar) : "memory");
}
__device__ __forceinline__ void mbar_wait(uint32_t a, uint32_t phase) {
    asm volatile(
        "{\n\t.reg .pred p;\n"
        "W%=:\n\t"
        "mbarrier.try_wait.parity.shared.b64 p, [%0], %1;\n\t"
        "@!p bra W%=;\n\t}"
        :: "r"(a), "r"(phase) : "memory");
}

// ---------------------------------------------------------------------------
// Kernel 1: logits = x @ W, top-2, softmax. x delivered by 1D TMA bulk into
// an 8-slot smem ring (bypasses the per-SM L1tex LDG queue that capped every
// register-load variant at ~2.1 TB/s). Warp w owns slot w: computes 2 tokens
// (full D, f32x2 FMA vs smem-transposed W), refills its slot, computes 2 more.
// ---------------------------------------------------------------------------
__global__ __launch_bounds__(BLK1) void k_logits_topk(
        const float* __restrict__ x,
        const float* __restrict__ W,
        float* __restrict__ out) {
    extern __shared__ char smem_raw[];
    float* wt = reinterpret_cast<float*>(smem_raw + SMEM_WT_OFF);

    int tid  = threadIdx.x;
    int lane = tid & 31;
    int wrp  = tid >> 5;
    int tok_base = blockIdx.x * 32;

    uint32_t mb = smem_u32(smem_raw) + wrp * 8;   // this warp's mbarrier

    // init 8 mbarriers (count=1 each)
    if (tid < NSLOT) mbar_init(smem_u32(smem_raw) + tid * 8, 1);
    __syncthreads();

    // each warp's lane 0 issues the TMA for its slot (stage A: tokens 2w,2w+1)
    uint32_t xs_dst = smem_u32(smem_raw) + SMEM_XS_OFF + wrp * STAGE_BYTES;
    const char* xsrc = reinterpret_cast<const char*>(x) + (size_t)tok_base * 8192;
    if (lane == 0) {
        mbar_expect_tx(mb, STAGE_BYTES);
        bulk_g2s(xs_dst, xsrc + (size_t)(2 * wrp) * 8192, STAGE_BYTES, mb);
    }

    // stage ALL of W transposed (overlaps TMA): wt[e][d]
    for (int idx = tid; idx < D_DIM * N_EXP; idx += BLK1) {
        int d = idx >> 3;
        int e = idx & 7;
        wt[e * PITCH + d] = W[idx];
    }
    __syncthreads();

    const ulonglong2* xsl = reinterpret_cast<const ulonglong2*>(
        smem_raw + SMEM_XS_OFF + wrp * STAGE_BYTES);

    float* gate = out + (size_t)N_TOK * N_EXP * CAP;
    float* idxf = gate + N_TOK * TOPK;

    #pragma unroll
    for (int stage = 0; stage < 2; stage++) {
        mbar_wait(mb, stage);                 // parity 0 then 1

        unsigned long long acc0[N_EXP] = {};
        unsigned long long acc1[N_EXP] = {};

        #pragma unroll 4
        for (int j = 0; j < 16; j++) {
            int f4 = j * 32 + lane;                       // [0,512)
            ulonglong2 xv0 = xsl[f4];                     // token A
            ulonglong2 xv1 = xsl[512 + f4];               // token B
            int dbase = f4 * 4;
            #pragma unroll
            for (int e = 0; e < N_EXP; e++) {
                ulonglong2 w = *reinterpret_cast<const ulonglong2*>(&wt[e * PITCH + dbase]);
                acc0[e] = fma2(xv0.x, w.x, acc0[e]);
                acc0[e] = fma2(xv0.y, w.y, acc0[e]);
                acc1[e] = fma2(xv1.x, w.x, acc1[e]);
                acc1[e] = fma2(xv1.y, w.y, acc1[e]);
            }
        }

        // horizontal add + butterfly reduce
        float logit[2][N_EXP];
        #pragma unroll
        for (int e = 0; e < N_EXP; e++) {
            float s0 = __uint_as_float((unsigned int)(acc0[e] & 0xffffffffull)) +
                       __uint_as_float((unsigned int)(acc0[e] >> 32));
            float s1 = __uint_as_float((unsigned int)(acc1[e] & 0xffffffffull)) +
                       __uint_as_float((unsigned int)(acc1[e] >> 32));
            #pragma unroll
            for (int off = 16; off > 0; off >>= 1) {
                s0 += __shfl_xor_sync(0xffffffffu, s0, off);
                s1 += __shfl_xor_sync(0xffffffffu, s1, off);
            }
            logit[0][e] = s0;
            logit[1][e] = s1;
        }

        int t0 = tok_base + stage * 16 + 2 * wrp;
        if (lane == 0) {
            #pragma unroll
            for (int t = 0; t < 2; t++) {
                int tok = t0 + t;
                float best = -INFINITY, sec = -INFINITY;
                int bi = 0, si = 0;
                #pragma unroll
                for (int e = 0; e < N_EXP; e++) {
                    float v = logit[t][e];
                    if (v > best)     { sec = best; si = bi; best = v; bi = e; }
                    else if (v > sec) { sec = v;    si = e; }
                }
                float g0 = 1.0f / (1.0f + expf(sec - best));
                gate[tok * 2 + 0] = g0;
                gate[tok * 2 + 1] = 1.0f - g0;
                idxf[tok * 2 + 0] = (float)bi;
                idxf[tok * 2 + 1] = (float)si;
                g_choice[tok * 2 + 0] = bi;
                g_choice[tok * 2 + 1] = si;
            }
        }

        // refill own slot for stage B (tokens 16+2w) — accs consumed above,
        // so all LDS reads of this slot have completed.
        if (stage == 0 && lane == 0) {
            mbar_expect_tx(mb, STAGE_BYTES);
            bulk_g2s(xs_dst, xsrc + (size_t)(16 + 2 * wrp) * 8192, STAGE_BYTES, mb);
        }
    }
}

// ---------------------------------------------------------------------------
// Kernel 2: per-(k,expert) running-count prefix scan. (R2-proven)
// ---------------------------------------------------------------------------
__global__ void k_scan() {
    int k = blockIdx.x >> 3;
    int e = blockIdx.x & 7;
    int tid  = threadIdx.x;
    int lane = tid & 31;
    int wid  = tid >> 5;

    __shared__ int warp_sums[32];

    int n0 = tid * 4;
    int flags[4];
    int localex[4];
    int s = 0;
    #pragma unroll
    for (int j = 0; j < 4; j++) {
        flags[j]   = (g_choice[(n0 + j) * 2 + k] == e) ? 1 : 0;
        localex[j] = s;
        s += flags[j];
    }

    int inc = s;
    #pragma unroll
    for (int off = 1; off < 32; off <<= 1) {
        int v = __shfl_up_sync(0xffffffffu, inc, off);
        if (lane >= off) inc += v;
    }
    if (lane == 31) warp_sums[wid] = inc;
    __syncthreads();

    if (wid == 0) {
        int v = warp_sums[lane];
        int winc = v;
        #pragma unroll
        for (int off = 1; off < 32; off <<= 1) {
            int u = __shfl_up_sync(0xffffffffu, winc, off);
            if (lane >= off) winc += u;
        }
        warp_sums[lane] = winc - v;
    }
    __syncthreads();

    int thread_prefix = warp_sums[wid] + (inc - s);

    #pragma unroll
    for (int j = 0; j < 4; j++) {
        if (flags[j]) {
            int pri = thread_prefix + localex[j] + 1;
            g_slot[(n0 + j) * 2 + k] = (pri <= CAP) ? (pri - 1) : -1;
        }
    }
}

// ---------------------------------------------------------------------------
// Kernel 3 (fused zero+scatter): one block per token row. (R2-proven)
// ---------------------------------------------------------------------------
__global__ __launch_bounds__(256) void k_fill(float4* __restrict__ out) {
    int n   = blockIdx.x;
    int tid = threadIdx.x;

    int c0 = g_choice[n * 2 + 0];
    int c1 = g_choice[n * 2 + 1];
    int s0 = g_slot[n * 2 + 0];
    int s1 = g_slot[n * 2 + 1];
    int o0 = (s0 >= 0) ? c0 * CAP + s0 : -1;
    int o1 = (s1 >= 0) ? c1 * CAP + s1 : -1;

    float4* row = out + (size_t)n * (N_EXP * CAP / 4);

    #pragma unroll
    for (int q = 0; q < 4; q++) {
        int g = q * 256 + tid;
        int f = g * 4;
        float4 v;
        v.x = (o0 == f     || o1 == f    ) ? 1.0f : 0.0f;
        v.y = (o0 == f + 1 || o1 == f + 1) ? 1.0f : 0.0f;
        v.z = (o0 == f + 2 || o1 == f + 2) ? 1.0f : 0.0f;
        v.w = (o0 == f + 3 || o1 == f + 3) ? 1.0f : 0.0f;
        row[g] = v;
    }
}

// ---------------------------------------------------------------------------
extern "C" void kernel_launch(void* const* d_in, const int* in_sizes, int n_in,
                              void* d_out, int out_size) {
    const float* x = (const float*)d_in[0];   // [4096, 2048]
    const float* W = (const float*)d_in[1];   // [2048, 8]
    float* out = (float*)d_out;

    cudaFuncSetAttribute(k_logits_topk,
                         cudaFuncAttributeMaxDynamicSharedMemorySize, DYN_SMEM);

    k_logits_topk<<<GRID1, BLK1, DYN_SMEM>>>(x, W, out);
    k_scan<<<16, 1024>>>();
    k_fill<<<N_TOK, 256>>>((float4*)out);
}

// round 13
// speedup vs baseline: 1.3224x; 1.3224x over previous
#include <cuda_runtime.h>
#include <math.h>

#define N_TOK 4096
#define D_DIM 2048
#define N_EXP 8
#define TOPK  2
#define CAP   512
#define PITCH 2052                 // padded W smem row (floats)
#define BLK1  768                  // 24 warps: 16 GEMM + 8 fill
#define GRID1 128                  // 1 block/SM, single balanced wave

__device__ int g_choice[N_TOK * TOPK];

__device__ __forceinline__ unsigned long long fma2(
        unsigned long long a, unsigned long long b, unsigned long long c) {
    unsigned long long d;
    asm("fma.rn.f32x2 %0, %1, %2, %3;" : "=l"(d) : "l"(a), "l"(b), "l"(c));
    return d;
}

// ---------------------------------------------------------------------------
// Kernel 1 (warp-specialized): warps 0-15 compute logits/top-2/softmax for
// 32 tokens (2 per warp, f32x2 FMA vs full transposed-W in smem); warps 16-23
// zero this block's 512 KB slice of the dispatcher concurrently. Stores ride
// the store path while GEMM warps stall on the LDG-return path.
// ---------------------------------------------------------------------------
__global__ __launch_bounds__(BLK1) void k_fused(
        const float* __restrict__ x,
        const float* __restrict__ W,
        float* __restrict__ out) {
    __shared__ float wt[N_EXP * PITCH];   // 65.7 KB

    int tid  = threadIdx.x;
    int lane = tid & 31;
    int wrp  = tid >> 5;
    int bid  = blockIdx.x;

    // stage ALL of W transposed: wt[e][d]  (all 24 warps help)
    for (int idx = tid; idx < D_DIM * N_EXP; idx += BLK1) {
        int d = idx >> 3;
        int e = idx & 7;
        wt[e * PITCH + d] = W[idx];
    }
    __syncthreads();

    if (wrp >= 16) {
        // ---------------- fill warps: zero 64 KB each ----------------
        int f = wrp - 16;
        float4* z4 = reinterpret_cast<float4*>(out);
        size_t base = (size_t)bid * 32768 + f * 4096 + lane;   // f4 units
        const float4 zero = make_float4(0.f, 0.f, 0.f, 0.f);
        #pragma unroll 8
        for (int i = 0; i < 128; i++)
            z4[base + i * 32] = zero;
        return;
    }

    // ---------------- GEMM warps: 2 tokens each ----------------
    int t0 = (bid * 16 + wrp) * 2;
    const ulonglong2* xr0 = reinterpret_cast<const ulonglong2*>(x) + (size_t)t0 * (D_DIM / 4);
    const ulonglong2* xr1 = xr0 + (D_DIM / 4);

    unsigned long long acc0[N_EXP] = {};
    unsigned long long acc1[N_EXP] = {};

    // double-buffered 2-j prefetch: 4 LDG.128 in flight per warp
    ulonglong2 xa[2][2], xb[2][2];
    xa[0][0] = xr0[lane];      xb[0][0] = xr1[lane];
    xa[0][1] = xr0[32 + lane]; xb[0][1] = xr1[32 + lane];

    #pragma unroll
    for (int jj = 0; jj < 8; jj++) {
        int cur = jj & 1, nxt = cur ^ 1;
        if (jj < 7) {
            int j2 = (jj + 1) * 2;
            xa[nxt][0] = xr0[(j2    ) * 32 + lane];
            xb[nxt][0] = xr1[(j2    ) * 32 + lane];
            xa[nxt][1] = xr0[(j2 + 1) * 32 + lane];
            xb[nxt][1] = xr1[(j2 + 1) * 32 + lane];
        }
        #pragma unroll
        for (int u = 0; u < 2; u++) {
            int dbase = ((jj * 2 + u) * 32 + lane) * 4;
            #pragma unroll
            for (int e = 0; e < N_EXP; e++) {
                ulonglong2 w = *reinterpret_cast<const ulonglong2*>(&wt[e * PITCH + dbase]);
                acc0[e] = fma2(xa[cur][u].x, w.x, acc0[e]);
                acc0[e] = fma2(xa[cur][u].y, w.y, acc0[e]);
                acc1[e] = fma2(xb[cur][u].x, w.x, acc1[e]);
                acc1[e] = fma2(xb[cur][u].y, w.y, acc1[e]);
            }
        }
    }

    // horizontal add + butterfly reduce
    float logit[2][N_EXP];
    #pragma unroll
    for (int e = 0; e < N_EXP; e++) {
        float s0 = __uint_as_float((unsigned int)(acc0[e] & 0xffffffffull)) +
                   __uint_as_float((unsigned int)(acc0[e] >> 32));
        float s1 = __uint_as_float((unsigned int)(acc1[e] & 0xffffffffull)) +
                   __uint_as_float((unsigned int)(acc1[e] >> 32));
        #pragma unroll
        for (int off = 16; off > 0; off >>= 1) {
            s0 += __shfl_xor_sync(0xffffffffu, s0, off);
            s1 += __shfl_xor_sync(0xffffffffu, s1, off);
        }
        logit[0][e] = s0;
        logit[1][e] = s1;
    }

    if (lane == 0) {
        float* gate = out + (size_t)N_TOK * N_EXP * CAP;
        float* idxf = gate + N_TOK * TOPK;
        #pragma unroll
        for (int t = 0; t < 2; t++) {
            int tok = t0 + t;
            float best = -INFINITY, sec = -INFINITY;
            int bi = 0, si = 0;
            #pragma unroll
            for (int e = 0; e < N_EXP; e++) {
                float v = logit[t][e];
                if (v > best)     { sec = best; si = bi; best = v; bi = e; }
                else if (v > sec) { sec = v;    si = e; }
            }
            float g0 = 1.0f / (1.0f + expf(sec - best));
            gate[tok * 2 + 0] = g0;
            gate[tok * 2 + 1] = 1.0f - g0;
            idxf[tok * 2 + 0] = (float)bi;
            idxf[tok * 2 + 1] = (float)si;
            g_choice[tok * 2 + 0] = bi;
            g_choice[tok * 2 + 1] = si;
        }
    }
}

// ---------------------------------------------------------------------------
// Kernel 2: per-(k,expert) prefix scan + scatter of the 1.0f entries into
// the (already zeroed) dispatcher. 16 blocks, 1024 threads. (R3-proven)
// ---------------------------------------------------------------------------
__global__ void k_scan_scatter(float* __restrict__ out) {
    int k = blockIdx.x >> 3;
    int e = blockIdx.x & 7;
    int tid  = threadIdx.x;
    int lane = tid & 31;
    int wid  = tid >> 5;

    __shared__ int warp_sums[32];

    int n0 = tid * 4;
    int flags[4];
    int localex[4];
    int s = 0;
    #pragma unroll
    for (int j = 0; j < 4; j++) {
        flags[j]   = (g_choice[(n0 + j) * 2 + k] == e) ? 1 : 0;
        localex[j] = s;
        s += flags[j];
    }

    int inc = s;
    #pragma unroll
    for (int off = 1; off < 32; off <<= 1) {
        int v = __shfl_up_sync(0xffffffffu, inc, off);
        if (lane >= off) inc += v;
    }
    if (lane == 31) warp_sums[wid] = inc;
    __syncthreads();

    if (wid == 0) {
        int v = warp_sums[lane];
        int winc = v;
        #pragma unroll
        for (int off = 1; off < 32; off <<= 1) {
            int u = __shfl_up_sync(0xffffffffu, winc, off);
            if (lane >= off) winc += u;
        }
        warp_sums[lane] = winc - v;
    }
    __syncthreads();

    int thread_prefix = warp_sums[wid] + (inc - s);

    #pragma unroll
    for (int j = 0; j < 4; j++) {
        if (flags[j]) {
            int pri = thread_prefix + localex[j] + 1;   // 1-based priority
            if (pri <= CAP)
                out[(size_t)(n0 + j) * (N_EXP * CAP) + e * CAP + (pri - 1)] = 1.0f;
        }
    }
}

// ---------------------------------------------------------------------------
extern "C" void kernel_launch(void* const* d_in, const int* in_sizes, int n_in,
                              void* d_out, int out_size) {
    const float* x = (const float*)d_in[0];   // [4096, 2048]
    const float* W = (const float*)d_in[1];   // [2048, 8]
    float* out = (float*)d_out;

    k_fused<<<GRID1, BLK1>>>(x, W, out);
    k_scan_scatter<<<16, 1024>>>(out);
}